// round 1
// baseline (speedup 1.0000x reference)
#include <cuda_runtime.h>
#include <cstdint>

// Problem constants
#define BATCH   8192
#define DIMN    4096
#define HIDN    256
#define NHEAD   16
#define SEQL    2048
// DECAY_CONSTANT = SEQ // 512 = 4  ->  exponent 0.25

// 128 MiB scratch for the intermediate "hidden" activation [BATCH, DIMN]
__device__ float g_hidden[(size_t)BATCH * DIMN];

// ---------------------------------------------------------------------------
// Tiled SGEMM, 128x128 block tile, BK=8, 256 threads, 8x8 per-thread tile.
// MODE 1: A = x [M,K], B = W_proj viewed as [K, H*HID] (per-head slices),
//         epilogue: hidden = w*(acc + b_proj) + coef*caches + b_mix
// MODE 2: A = hidden [M,K], B = W_out [K,N], epilogue: + b_out
// All dims are multiples of the tile sizes; no bounds checks needed.
// ---------------------------------------------------------------------------
template <int MODE>
__global__ __launch_bounds__(256)
void sgemm_fused(const float* __restrict__ A,
                 const float* __restrict__ Bmat,
                 float* __restrict__ C,
                 const float* __restrict__ b_proj,
                 const float* __restrict__ w_mix,
                 const float* __restrict__ b_mix,
                 const float* __restrict__ decay_values,
                 const float* __restrict__ caches,
                 const int*   __restrict__ index_p,
                 const float* __restrict__ b_out,
                 int M, int N, int K)
{
    constexpr int BM = 128, BN = 128, BK = 8;

    __shared__ float As[BK][BM];
    __shared__ float Bs[BK][BN];

    const int tid = threadIdx.x;
    const int bx = blockIdx.x;   // N tiles
    const int by = blockIdx.y;   // M tiles

    const int row0 = by * BM;
    const int j0   = bx * BN;

    // B operand addressing
    const float* Bsrc;
    int ldb;
    int h = 0, k0 = 0;
    if (MODE == 1) {
        h  = j0 >> 8;        // head index (BN=128 tile never crosses a head)
        k0 = j0 & 255;       // 0 or 128 within the head's HID columns
        Bsrc = Bmat + (size_t)h * K * HIDN + k0;
        ldb  = HIDN;
    } else {
        Bsrc = Bmat + j0;
        ldb  = N;
    }

    // global->shared load mapping
    const int aRow = tid >> 1;            // 0..127
    const int aCol = (tid & 1) * 4;       // 0 or 4
    const int bRow = tid >> 5;            // 0..7
    const int bCol = (tid & 31) * 4;      // 0..124

    const float* Aptr = A + (size_t)(row0 + aRow) * K + aCol;

    // compute mapping: 16x16 threads, each 8x8
    const int tRow = (tid >> 4) * 8;
    const int tCol = (tid & 15) * 8;

    float acc[8][8];
    #pragma unroll
    for (int i = 0; i < 8; i++)
        #pragma unroll
        for (int j = 0; j < 8; j++)
            acc[i][j] = 0.0f;

    for (int kt = 0; kt < K; kt += BK) {
        // load A tile (transposed into As[k][m])
        float4 av = *reinterpret_cast<const float4*>(Aptr + kt);
        As[aCol + 0][aRow] = av.x;
        As[aCol + 1][aRow] = av.y;
        As[aCol + 2][aRow] = av.z;
        As[aCol + 3][aRow] = av.w;
        // load B tile
        float4 bv = *reinterpret_cast<const float4*>(
            Bsrc + (size_t)(kt + bRow) * ldb + bCol);
        *reinterpret_cast<float4*>(&Bs[bRow][bCol]) = bv;
        __syncthreads();

        #pragma unroll
        for (int k = 0; k < BK; k++) {
            float a[8], b[8];
            #pragma unroll
            for (int i = 0; i < 8; i++) a[i] = As[k][tRow + i];
            #pragma unroll
            for (int j = 0; j < 8; j++) b[j] = Bs[k][tCol + j];
            #pragma unroll
            for (int i = 0; i < 8; i++)
                #pragma unroll
                for (int j = 0; j < 8; j++)
                    acc[i][j] = fmaf(a[i], b[j], acc[i][j]);
        }
        __syncthreads();
    }

    // ---------------- epilogue ----------------
    if (MODE == 1) {
        const int idx = *index_p;
        float dv = decay_values[h];
        dv = fminf(fmaxf(dv, 0.9f), 1.0f);
        const float decay = sqrtf(sqrtf(dv));          // dv^(1/4)
        const float w   = w_mix[(size_t)h * SEQL + idx];
        const float bb  = b_mix[(size_t)h * SEQL + idx];
        const float coef = (h < NHEAD / 2) ? (w * decay) : decay;

        #pragma unroll
        for (int i = 0; i < 8; i++) {
            const int r = row0 + tRow + i;
            const size_t cacheRow = (size_t)h * BATCH * HIDN + (size_t)r * HIDN;
            #pragma unroll
            for (int j = 0; j < 8; j++) {
                const int cc = tCol + j;        // col within tile
                const int k  = k0 + cc;         // col within head (0..255)
                float v = w * (acc[i][j] + b_proj[h * HIDN + k])
                        + coef * caches[cacheRow + k]
                        + bb;
                C[(size_t)r * N + j0 + cc] = v;
            }
        }
    } else {
        #pragma unroll
        for (int i = 0; i < 8; i++) {
            const int r = row0 + tRow + i;
            #pragma unroll
            for (int j = 0; j < 8; j++) {
                const int cc = j0 + tCol + j;
                C[(size_t)r * N + cc] = acc[i][j] + b_out[cc];
            }
        }
    }
}

extern "C" void kernel_launch(void* const* d_in, const int* in_sizes, int n_in,
                              void* d_out, int out_size)
{
    const float* x       = (const float*)d_in[0];
    const int*   index_p = (const int*)  d_in[1];
    const float* W_proj  = (const float*)d_in[2];
    const float* b_proj  = (const float*)d_in[3];
    const float* W_out   = (const float*)d_in[4];
    const float* b_out   = (const float*)d_in[5];
    const float* w_mix   = (const float*)d_in[6];
    const float* b_mix   = (const float*)d_in[7];
    const float* decay   = (const float*)d_in[8];
    const float* caches  = (const float*)d_in[9];
    float* out = (float*)d_out;

    float* hidden = nullptr;
    cudaGetSymbolAddress((void**)&hidden, g_hidden);

    dim3 block(256);
    dim3 grid1(DIMN / 128, BATCH / 128);
    sgemm_fused<1><<<grid1, block>>>(x, W_proj, hidden,
                                     b_proj, w_mix, b_mix, decay, caches,
                                     index_p, b_out,
                                     BATCH, DIMN, DIMN);

    dim3 grid2(DIMN / 128, BATCH / 128);
    sgemm_fused<2><<<grid2, block>>>(hidden, W_out, out,
                                     b_proj, w_mix, b_mix, decay, caches,
                                     index_p, b_out,
                                     BATCH, DIMN, DIMN);
}

// round 3
// speedup vs baseline: 4.3415x; 4.3415x over previous
#include <cuda_runtime.h>
#include <cstdint>

#define BATCH 8192
#define DIMN  4096
#define HIDN  256
#define NHEAD 16
#define SEQL  2048

// Static scratch (allocation-free)
__device__ float g_hidden[(size_t)BATCH * DIMN];   // tf32-rounded hidden
__device__ float g_xr[(size_t)BATCH * DIMN];       // tf32-rounded x
__device__ float g_bt1[(size_t)DIMN * DIMN];       // W_proj^T per head: [(h*256+n)][k]
__device__ float g_bt2[(size_t)DIMN * DIMN];       // W_out^T: [n][k]

__device__ __forceinline__ float rna_tf32(float x) {
    float r;
    asm("cvt.rna.tf32.f32 %0, %1;" : "=f"(r) : "f"(x));
    return r;
}
__device__ __forceinline__ uint32_t smem_u32(const void* p) {
    uint32_t a;
    asm("{ .reg .u64 t; cvta.to.shared.u64 t, %1; cvt.u32.u64 %0, t; }"
        : "=r"(a) : "l"(p));
    return a;
}

// ---------------------------------------------------------------------------
// Pre-pass kernels
// ---------------------------------------------------------------------------
__global__ void round_tf32_kernel(const float4* __restrict__ src,
                                  float4* __restrict__ dst, int n4) {
    int i = blockIdx.x * blockDim.x + threadIdx.x;
    if (i < n4) {
        float4 v = src[i];
        v.x = rna_tf32(v.x); v.y = rna_tf32(v.y);
        v.z = rna_tf32(v.z); v.w = rna_tf32(v.w);
        dst[i] = v;
    }
}

// src: batch b of [R][C] row-major.  dst[(b*C + c)*R + r] = rna(src[r][c])
__global__ void transpose_round_kernel(const float* __restrict__ src,
                                       float* __restrict__ dst, int R, int C) {
    __shared__ float tile[32][33];
    const int b = blockIdx.z;
    const float* s = src + (size_t)b * R * C;
    const int c0 = blockIdx.x * 32, r0 = blockIdx.y * 32;
    const int tx = threadIdx.x, ty = threadIdx.y;
    #pragma unroll
    for (int j = 0; j < 4; j++)
        tile[ty + 8 * j][tx] = rna_tf32(s[(size_t)(r0 + ty + 8 * j) * C + c0 + tx]);
    __syncthreads();
    #pragma unroll
    for (int j = 0; j < 4; j++)
        dst[(size_t)(b * C + c0 + ty + 8 * j) * R + r0 + tx] = tile[tx][ty + 8 * j];
}

// ---------------------------------------------------------------------------
// tf32 mma.sync GEMM. CTA 128x128x32, 3-stage cp.async, 8 warps (2M x 4N),
// warp tile 64x32, mma m16n8k8. A [M,K] row-major, B [N,K] n-major (= col-major B).
// MODE 1: C = rna( w*(acc+b_proj) + coef*cache + b_mix )   (per-head scalars)
// MODE 2: C = acc + b_out
// ---------------------------------------------------------------------------
template <int MODE>
__global__ __launch_bounds__(256)
void gemm_tf32mma(const float* __restrict__ A, const float* __restrict__ B,
                  float* __restrict__ C,
                  const float* __restrict__ b_proj, const float* __restrict__ w_mix,
                  const float* __restrict__ b_mix, const float* __restrict__ decay_values,
                  const float* __restrict__ caches, const int* __restrict__ index_p,
                  const float* __restrict__ b_out)
{
    constexpr int BK = 32;
    constexpr int NS = 3;
    constexpr int NT = DIMN / BK;              // 128 k-slabs
    constexpr int STAGE_FLOATS = 2 * 128 * BK; // A(16KB) + B(16KB)

    extern __shared__ float smem[];

    const int tid  = threadIdx.x;
    const int wid  = tid >> 5;
    const int lane = tid & 31;
    const int warpM = wid & 1;    // 0..1
    const int warpN = wid >> 1;   // 0..3
    const int grp = lane >> 2;    // 0..7
    const int tig = lane & 3;     // 0..3

    const int row0 = blockIdx.y * 128;
    const int n0   = blockIdx.x * 128;
    const float* aBase = A + (size_t)row0 * DIMN;
    const float* bBase = B + (size_t)n0 * DIMN;

    // ---- async tile loader: 128 rows x 8 chunks(16B) each for A and B ----
    auto load = [&](int s, int kt) {
        const uint32_t sA = smem_u32(smem + s * STAGE_FLOATS);
        const uint32_t sB = sA + 16384;
        #pragma unroll
        for (int i = 0; i < 4; i++) {
            const int g = tid + i * 256;       // 0..1023
            const int r = g >> 3, ch = g & 7;
            const uint32_t swoff = (uint32_t)(r * 128 + ((ch ^ (r & 7)) << 4));
            const float* srcA = aBase + (size_t)r * DIMN + kt + ch * 4;
            const float* srcB = bBase + (size_t)r * DIMN + kt + ch * 4;
            asm volatile("cp.async.cg.shared.global [%0], [%1], 16;"
                         :: "r"(sA + swoff), "l"(srcA));
            asm volatile("cp.async.cg.shared.global [%0], [%1], 16;"
                         :: "r"(sB + swoff), "l"(srcB));
        }
        asm volatile("cp.async.commit_group;");
    };

    float acc[4][4][4];
    #pragma unroll
    for (int mi = 0; mi < 4; mi++)
        #pragma unroll
        for (int ni = 0; ni < 4; ni++)
            #pragma unroll
            for (int v = 0; v < 4; v++) acc[mi][ni][v] = 0.0f;

    load(0, 0);
    load(1, BK);

    for (int t = 0; t < NT; t++) {
        if (t < NT - 1) asm volatile("cp.async.wait_group 1;" ::: "memory");
        else            asm volatile("cp.async.wait_group 0;" ::: "memory");
        __syncthreads();

        if (t + 2 < NT) load((t + 2) % NS, (t + 2) * BK);

        const char* stA = (const char*)(smem + (t % NS) * STAGE_FLOATS);
        const char* stB = stA + 16384;

        #pragma unroll
        for (int ki = 0; ki < 4; ki++) {
            // A fragments
            uint32_t a[4][4];
            #pragma unroll
            for (int mi = 0; mi < 4; mi++) {
                const int r0 = warpM * 64 + mi * 16 + grp;
                const int r1 = r0 + 8;
                const int c4 = tig * 4;
                const int ch0 = ki * 2, ch1 = ki * 2 + 1;
                a[mi][0] = *(const uint32_t*)(stA + r0 * 128 + ((ch0 ^ (r0 & 7)) << 4) + c4);
                a[mi][1] = *(const uint32_t*)(stA + r1 * 128 + ((ch0 ^ (r1 & 7)) << 4) + c4);
                a[mi][2] = *(const uint32_t*)(stA + r0 * 128 + ((ch1 ^ (r0 & 7)) << 4) + c4);
                a[mi][3] = *(const uint32_t*)(stA + r1 * 128 + ((ch1 ^ (r1 & 7)) << 4) + c4);
            }
            // B fragments
            uint32_t b[4][2];
            #pragma unroll
            for (int ni = 0; ni < 4; ni++) {
                const int nr = warpN * 32 + ni * 8 + grp;
                const int c4 = tig * 4;
                const int ch0 = ki * 2, ch1 = ki * 2 + 1;
                b[ni][0] = *(const uint32_t*)(stB + nr * 128 + ((ch0 ^ (nr & 7)) << 4) + c4);
                b[ni][1] = *(const uint32_t*)(stB + nr * 128 + ((ch1 ^ (nr & 7)) << 4) + c4);
            }
            #pragma unroll
            for (int mi = 0; mi < 4; mi++)
                #pragma unroll
                for (int ni = 0; ni < 4; ni++)
                    asm volatile(
                        "mma.sync.aligned.m16n8k8.row.col.f32.tf32.tf32.f32 "
                        "{%0,%1,%2,%3}, {%4,%5,%6,%7}, {%8,%9}, {%0,%1,%2,%3};"
                        : "+f"(acc[mi][ni][0]), "+f"(acc[mi][ni][1]),
                          "+f"(acc[mi][ni][2]), "+f"(acc[mi][ni][3])
                        : "r"(a[mi][0]), "r"(a[mi][1]), "r"(a[mi][2]), "r"(a[mi][3]),
                          "r"(b[ni][0]), "r"(b[ni][1]));
        }
    }

    // ------------------------------ epilogue ------------------------------
    if (MODE == 1) {
        const int h  = blockIdx.x >> 1;
        const int k0 = (blockIdx.x & 1) * 128;
        const int idx = *index_p;
        float dv = fminf(fmaxf(decay_values[h], 0.9f), 1.0f);
        const float decay = sqrtf(sqrtf(dv));
        const float w  = w_mix[(size_t)h * SEQL + idx];
        const float bb = b_mix[(size_t)h * SEQL + idx];
        const float coef = (h < NHEAD / 2) ? (w * decay) : decay;

        #pragma unroll
        for (int mi = 0; mi < 4; mi++) {
            #pragma unroll
            for (int half = 0; half < 2; half++) {
                const int r = row0 + warpM * 64 + mi * 16 + grp + half * 8;
                const float* cacheRow = caches + ((size_t)h * BATCH + r) * HIDN;
                float* Crow = C + (size_t)r * DIMN + n0;
                #pragma unroll
                for (int ni = 0; ni < 4; ni++) {
                    #pragma unroll
                    for (int e = 0; e < 2; e++) {
                        const int cc = warpN * 32 + ni * 8 + tig * 2 + e;
                        const int k  = k0 + cc;
                        const float av = acc[mi][ni][half * 2 + e];
                        float v = w * (av + b_proj[h * HIDN + k])
                                + coef * cacheRow[k] + bb;
                        Crow[cc] = rna_tf32(v);
                    }
                }
            }
        }
    } else {
        #pragma unroll
        for (int mi = 0; mi < 4; mi++) {
            #pragma unroll
            for (int half = 0; half < 2; half++) {
                const int r = row0 + warpM * 64 + mi * 16 + grp + half * 8;
                float* Crow = C + (size_t)r * DIMN + n0;
                #pragma unroll
                for (int ni = 0; ni < 4; ni++) {
                    #pragma unroll
                    for (int e = 0; e < 2; e++) {
                        const int cc = warpN * 32 + ni * 8 + tig * 2 + e;
                        Crow[cc] = acc[mi][ni][half * 2 + e] + b_out[n0 + cc];
                    }
                }
            }
        }
    }
}

// ---------------------------------------------------------------------------
extern "C" void kernel_launch(void* const* d_in, const int* in_sizes, int n_in,
                              void* d_out, int out_size)
{
    const float* x       = (const float*)d_in[0];
    const int*   index_p = (const int*)  d_in[1];
    const float* W_proj  = (const float*)d_in[2];
    const float* b_proj  = (const float*)d_in[3];
    const float* W_out   = (const float*)d_in[4];
    const float* b_out   = (const float*)d_in[5];
    const float* w_mix   = (const float*)d_in[6];
    const float* b_mix   = (const float*)d_in[7];
    const float* decay   = (const float*)d_in[8];
    const float* caches  = (const float*)d_in[9];
    float* out = (float*)d_out;

    float *hidden, *xr, *bt1, *bt2;
    cudaGetSymbolAddress((void**)&hidden, g_hidden);
    cudaGetSymbolAddress((void**)&xr,     g_xr);
    cudaGetSymbolAddress((void**)&bt1,    g_bt1);
    cudaGetSymbolAddress((void**)&bt2,    g_bt2);

    const int SMEM_DYN = 3 * 2 * 128 * 32 * 4;  // 96 KB
    cudaFuncSetAttribute(gemm_tf32mma<1>, cudaFuncAttributeMaxDynamicSharedMemorySize, SMEM_DYN);
    cudaFuncSetAttribute(gemm_tf32mma<2>, cudaFuncAttributeMaxDynamicSharedMemorySize, SMEM_DYN);

    {
        const int n4 = (BATCH * DIMN) / 4;
        round_tf32_kernel<<<(n4 + 255) / 256, 256>>>((const float4*)x, (float4*)xr, n4);
    }
    transpose_round_kernel<<<dim3(HIDN / 32, DIMN / 32, NHEAD), dim3(32, 8)>>>(
        W_proj, bt1, DIMN, HIDN);
    transpose_round_kernel<<<dim3(DIMN / 32, DIMN / 32, 1), dim3(32, 8)>>>(
        W_out, bt2, DIMN, DIMN);

    dim3 grid(DIMN / 128, BATCH / 128);   // 32 x 64
    gemm_tf32mma<1><<<grid, 256, SMEM_DYN>>>(xr, bt1, hidden,
                                             b_proj, w_mix, b_mix, decay, caches,
                                             index_p, b_out);
    gemm_tf32mma<2><<<grid, 256, SMEM_DYN>>>(hidden, bt2, out,
                                             b_proj, w_mix, b_mix, decay, caches,
                                             index_p, b_out);
}